// round 1
// baseline (speedup 1.0000x reference)
#include <cuda_runtime.h>

#define N_ROWS 16384
#define K_CODES 4096
#define D_DIM 512

#define BM 128
#define BN 128
#define BK 16
#define PAD 132   // 128 + 4, keeps 16B alignment, reduces store conflicts

// -------- scratch (no allocation allowed) --------
__device__ float g_znorm[N_ROWS];
__device__ float g_cnorm[K_CODES];
__device__ int   g_idx[N_ROWS];
__device__ float g_partial[N_ROWS];

// -------- packed f32x2 helpers --------
__device__ __forceinline__ unsigned long long pk2(float x, float y){
    unsigned long long r;
    asm("mov.b64 %0, {%1,%2};" : "=l"(r) : "f"(x), "f"(y));
    return r;
}
__device__ __forceinline__ void upk2(unsigned long long v, float& x, float& y){
    asm("mov.b64 {%0,%1}, %2;" : "=f"(x), "=f"(y) : "l"(v));
}
__device__ __forceinline__ unsigned long long ffma2(unsigned long long a,
                                                    unsigned long long b,
                                                    unsigned long long c){
    unsigned long long d;
    asm("fma.rn.f32x2 %0, %1, %2, %3;" : "=l"(d) : "l"(a), "l"(b), "l"(c));
    return d;
}

// -------- row-norm kernels (fp64 accumulate -> fp32, very accurate) --------
__global__ void znorm_kernel(const float* __restrict__ z){
    int w = (blockIdx.x * blockDim.x + threadIdx.x) >> 5;
    int lane = threadIdx.x & 31;
    if (w >= N_ROWS) return;
    const float* r = z + (size_t)w * D_DIM;
    double acc = 0.0;
    #pragma unroll 4
    for (int j = lane; j < D_DIM; j += 32){ float v = r[j]; acc += (double)v * (double)v; }
    #pragma unroll
    for (int o = 16; o > 0; o >>= 1) acc += __shfl_down_sync(0xffffffffu, acc, o);
    if (lane == 0) g_znorm[w] = (float)acc;
}

__global__ void cnorm_kernel(const float* __restrict__ cb){
    int w = (blockIdx.x * blockDim.x + threadIdx.x) >> 5;
    int lane = threadIdx.x & 31;
    if (w >= K_CODES) return;
    const float* r = cb + (size_t)w * D_DIM;
    double acc = 0.0;
    #pragma unroll 4
    for (int j = lane; j < D_DIM; j += 32){ float v = r[j]; acc += (double)v * (double)v; }
    #pragma unroll
    for (int o = 16; o > 0; o >>= 1) acc += __shfl_down_sync(0xffffffffu, acc, o);
    if (lane == 0) g_cnorm[w] = (float)acc;
}

// -------- main fused distance+argmin kernel --------
// grid: N_ROWS/BM = 128 blocks, 256 threads (16x16), TM=8, TN=8 per thread.
// dist replicates reference rounding: fp32(fp32(zn + cn) - 2*dot)
__global__ __launch_bounds__(256, 1)
void vq_argmin_kernel(const float* __restrict__ z, const float* __restrict__ cb)
{
    __shared__ __align__(16) union {
        struct { float A[BK][PAD]; float B[BK][PAD]; } t;
        struct { float v[128][17]; int id[128][17]; } r;
    } sm;

    const int tid = threadIdx.x;
    const int tx = tid & 15, ty = tid >> 4;
    const int tx4 = tx * 4, ty4 = ty * 4;
    const int rowbase = blockIdx.x * BM;

    // loading coords: each thread loads one float4 per 64-row half
    const int lrow = tid >> 2;          // 0..63
    const int lc4  = (tid & 3) * 4;     // 0,4,8,12

    const float* zp0 = z + (size_t)(rowbase + lrow) * D_DIM + lc4;
    const float* zp1 = zp0 + 64 * D_DIM;

    float znr[8];
    #pragma unroll
    for (int r = 0; r < 8; r++){
        int rl = (r < 4) ? (ty4 + r) : (64 + ty4 + r - 4);
        znr[r] = g_znorm[rowbase + rl];
    }

    float minv[8]; int mini[8];
    #pragma unroll
    for (int r = 0; r < 8; r++){ minv[r] = 3.4e38f; mini[r] = 0; }

    for (int ct = 0; ct < K_CODES / BN; ct++){
        const int cbase = ct * BN;
        const float* cp0 = cb + (size_t)(cbase + lrow) * D_DIM + lc4;
        const float* cp1 = cp0 + 64 * D_DIM;

        float cn[8];
        #pragma unroll
        for (int j = 0; j < 8; j++){
            int cl = (j < 4) ? (tx4 + j) : (64 + tx4 + j - 4);
            cn[j] = g_cnorm[cbase + cl];
        }

        unsigned long long acc[8][4];
        #pragma unroll
        for (int r = 0; r < 8; r++)
            #pragma unroll
            for (int p = 0; p < 4; p++) acc[r][p] = 0ull;

        // prefetch chunk 0
        float4 za0 = *(const float4*)zp0;
        float4 za1 = *(const float4*)zp1;
        float4 ca0 = *(const float4*)cp0;
        float4 ca1 = *(const float4*)cp1;

        for (int c = 0; c < D_DIM / BK; c++){
            // store prefetched chunk (transposed) to smem
            sm.t.A[lc4+0][lrow]    = za0.x; sm.t.A[lc4+1][lrow]    = za0.y;
            sm.t.A[lc4+2][lrow]    = za0.z; sm.t.A[lc4+3][lrow]    = za0.w;
            sm.t.A[lc4+0][64+lrow] = za1.x; sm.t.A[lc4+1][64+lrow] = za1.y;
            sm.t.A[lc4+2][64+lrow] = za1.z; sm.t.A[lc4+3][64+lrow] = za1.w;
            sm.t.B[lc4+0][lrow]    = ca0.x; sm.t.B[lc4+1][lrow]    = ca0.y;
            sm.t.B[lc4+2][lrow]    = ca0.z; sm.t.B[lc4+3][lrow]    = ca0.w;
            sm.t.B[lc4+0][64+lrow] = ca1.x; sm.t.B[lc4+1][64+lrow] = ca1.y;
            sm.t.B[lc4+2][64+lrow] = ca1.z; sm.t.B[lc4+3][64+lrow] = ca1.w;
            __syncthreads();

            // prefetch next chunk while computing this one
            if (c + 1 < D_DIM / BK){
                int d = (c + 1) * BK;
                za0 = *(const float4*)(zp0 + d);
                za1 = *(const float4*)(zp1 + d);
                ca0 = *(const float4*)(cp0 + d);
                ca1 = *(const float4*)(cp1 + d);
            }

            #pragma unroll
            for (int k = 0; k < BK; k++){
                float4 a0 = *(const float4*)&sm.t.A[k][ty4];
                float4 a1 = *(const float4*)&sm.t.A[k][64 + ty4];
                ulonglong2 b01 = *(const ulonglong2*)&sm.t.B[k][tx4];
                ulonglong2 b23 = *(const ulonglong2*)&sm.t.B[k][64 + tx4];
                unsigned long long bu0 = b01.x, bu1 = b01.y, bu2 = b23.x, bu3 = b23.y;
                float av[8] = {a0.x,a0.y,a0.z,a0.w,a1.x,a1.y,a1.z,a1.w};
                #pragma unroll
                for (int r = 0; r < 8; r++){
                    unsigned long long a2 = pk2(av[r], av[r]);
                    acc[r][0] = ffma2(a2, bu0, acc[r][0]);
                    acc[r][1] = ffma2(a2, bu1, acc[r][1]);
                    acc[r][2] = ffma2(a2, bu2, acc[r][2]);
                    acc[r][3] = ffma2(a2, bu3, acc[r][3]);
                }
            }
            __syncthreads();
        }

        // epilogue: dist = fp32(fp32(zn+cn) - 2*dot), running argmin (first-index ties)
        #pragma unroll
        for (int r = 0; r < 8; r++){
            #pragma unroll
            for (int p = 0; p < 4; p++){
                float slo, shi; upk2(acc[r][p], slo, shi);
                int j0 = 2 * p;
                int cl0 = (j0 < 4) ? (tx4 + j0) : (64 + tx4 + j0 - 4);
                int gc0 = cbase + cl0;
                float d0 = fmaf(-2.0f, slo, __fadd_rn(znr[r], cn[j0]));
                if (d0 < minv[r]){ minv[r] = d0; mini[r] = gc0; }
                float d1 = fmaf(-2.0f, shi, __fadd_rn(znr[r], cn[j0 + 1]));
                if (d1 < minv[r]){ minv[r] = d1; mini[r] = gc0 + 1; }
            }
        }
    }

    // cross-thread (per-row) reduction with index tie-break
    __syncthreads();
    #pragma unroll
    for (int r = 0; r < 8; r++){
        int rl = (r < 4) ? (ty4 + r) : (64 + ty4 + r - 4);
        sm.r.v[rl][tx]  = minv[r];
        sm.r.id[rl][tx] = mini[r];
    }
    __syncthreads();
    if (tid < 128){
        float bv = sm.r.v[tid][0]; int bi = sm.r.id[tid][0];
        #pragma unroll
        for (int j = 1; j < 16; j++){
            float vv = sm.r.v[tid][j]; int ii = sm.r.id[tid][j];
            if (vv < bv || (vv == bv && ii < bi)){ bv = vv; bi = ii; }
        }
        g_idx[rowbase + tid] = bi;
    }
}

// -------- gather z_q, per-row squared error, index output --------
__global__ void gather_kernel(const float* __restrict__ z, const float* __restrict__ cb,
                              float* __restrict__ out)
{
    __shared__ float red[128];
    int row = blockIdx.x, t = threadIdx.x;
    int id = g_idx[row];
    float4 cv = ((const float4*)(cb + (size_t)id  * D_DIM))[t];
    float4 zv = ((const float4*)(z  + (size_t)row * D_DIM))[t];
    ((float4*)(out + (size_t)row * D_DIM))[t] = cv;   // z_q_ste == z_q numerically
    float dx = zv.x - cv.x, dy = zv.y - cv.y, dz = zv.z - cv.z, dw = zv.w - cv.w;
    red[t] = dx*dx + dy*dy + dz*dz + dw*dw;
    __syncthreads();
    #pragma unroll
    for (int s = 64; s > 0; s >>= 1){
        if (t < s) red[t] += red[t + s];
        __syncthreads();
    }
    if (t == 0){
        g_partial[row] = red[0];
        out[(size_t)N_ROWS * D_DIM + row] = (float)id;   // encoding index
    }
}

// -------- deterministic final loss reduction --------
__global__ void loss_kernel(float* __restrict__ out){
    __shared__ double red[256];
    int t = threadIdx.x;
    double a = 0.0;
    for (int j = t; j < N_ROWS; j += 256) a += (double)g_partial[j];
    red[t] = a; __syncthreads();
    #pragma unroll
    for (int s = 128; s > 0; s >>= 1){
        if (t < s) red[t] += red[t + s];
        __syncthreads();
    }
    if (t == 0){
        float v = (float)(red[0] / ((double)N_ROWS * (double)D_DIM));
        // loss = codebook_loss + 0.25 * commitment_loss, numerically v + 0.25*v
        out[(size_t)N_ROWS * D_DIM + N_ROWS] = __fadd_rn(v, 0.25f * v);
    }
}

extern "C" void kernel_launch(void* const* d_in, const int* in_sizes, int n_in,
                              void* d_out, int out_size)
{
    const float* z  = (const float*)d_in[0];   // [16384, 512]
    const float* cb = (const float*)d_in[1];   // [4096, 512]
    float* out = (float*)d_out;                // [z_q (N*D)] [idx (N)] [loss (1)]

    znorm_kernel<<<N_ROWS / 8, 256>>>(z);      // 8 warps/block, 1 row/warp
    cnorm_kernel<<<K_CODES / 8, 256>>>(cb);
    vq_argmin_kernel<<<N_ROWS / BM, 256>>>(z, cb);
    gather_kernel<<<N_ROWS, 128>>>(z, cb, out);
    loss_kernel<<<1, 256>>>(out);
}

// round 2
// speedup vs baseline: 1.0036x; 1.0036x over previous
#include <cuda_runtime.h>

#define N_ROWS 16384
#define K_CODES 4096
#define D_DIM 512

#define BM 128
#define BN 128
#define BK 16
#define PAD 132   // 128 + 4, keeps 16B alignment, reduces store conflicts

// -------- scratch (no allocation allowed) --------
__device__ float g_znorm[N_ROWS];
__device__ float g_cnorm[K_CODES];
__device__ int   g_idx[N_ROWS];
__device__ float g_partial[N_ROWS];

// -------- packed f32x2 helpers --------
__device__ __forceinline__ unsigned long long pk2(float x, float y){
    unsigned long long r;
    asm("mov.b64 %0, {%1,%2};" : "=l"(r) : "f"(x), "f"(y));
    return r;
}
__device__ __forceinline__ void upk2(unsigned long long v, float& x, float& y){
    asm("mov.b64 {%0,%1}, %2;" : "=f"(x), "=f"(y) : "l"(v));
}
__device__ __forceinline__ unsigned long long ffma2(unsigned long long a,
                                                    unsigned long long b,
                                                    unsigned long long c){
    unsigned long long d;
    asm("fma.rn.f32x2 %0, %1, %2, %3;" : "=l"(d) : "l"(a), "l"(b), "l"(c));
    return d;
}

// -------- row-norm kernels (fp64 accumulate -> fp32, very accurate) --------
__global__ void znorm_kernel(const float* __restrict__ z){
    int w = (blockIdx.x * blockDim.x + threadIdx.x) >> 5;
    int lane = threadIdx.x & 31;
    if (w >= N_ROWS) return;
    const float* r = z + (size_t)w * D_DIM;
    double acc = 0.0;
    #pragma unroll 4
    for (int j = lane; j < D_DIM; j += 32){ float v = r[j]; acc += (double)v * (double)v; }
    #pragma unroll
    for (int o = 16; o > 0; o >>= 1) acc += __shfl_down_sync(0xffffffffu, acc, o);
    if (lane == 0) g_znorm[w] = (float)acc;
}

__global__ void cnorm_kernel(const float* __restrict__ cb){
    int w = (blockIdx.x * blockDim.x + threadIdx.x) >> 5;
    int lane = threadIdx.x & 31;
    if (w >= K_CODES) return;
    const float* r = cb + (size_t)w * D_DIM;
    double acc = 0.0;
    #pragma unroll 4
    for (int j = lane; j < D_DIM; j += 32){ float v = r[j]; acc += (double)v * (double)v; }
    #pragma unroll
    for (int o = 16; o > 0; o >>= 1) acc += __shfl_down_sync(0xffffffffu, acc, o);
    if (lane == 0) g_cnorm[w] = (float)acc;
}

// -------- main fused distance+argmin kernel --------
// grid: N_ROWS/BM = 128 blocks, 256 threads (16x16), TM=8, TN=8 per thread.
// dist replicates reference rounding: fp32(fp32(zn + cn) - 2*dot)
__global__ __launch_bounds__(256, 1)
void vq_argmin_kernel(const float* __restrict__ z, const float* __restrict__ cb)
{
    __shared__ __align__(16) union {
        struct { float A[BK][PAD]; float B[BK][PAD]; } t;
        struct { float v[128][17]; int id[128][17]; } r;
    } sm;

    const int tid = threadIdx.x;
    const int tx = tid & 15, ty = tid >> 4;
    const int tx4 = tx * 4, ty4 = ty * 4;
    const int rowbase = blockIdx.x * BM;

    // loading coords: each thread loads one float4 per 64-row half
    const int lrow = tid >> 2;          // 0..63
    const int lc4  = (tid & 3) * 4;     // 0,4,8,12

    const float* zp0 = z + (size_t)(rowbase + lrow) * D_DIM + lc4;
    const float* zp1 = zp0 + 64 * D_DIM;

    float znr[8];
    #pragma unroll
    for (int r = 0; r < 8; r++){
        int rl = (r < 4) ? (ty4 + r) : (64 + ty4 + r - 4);
        znr[r] = g_znorm[rowbase + rl];
    }

    float minv[8]; int mini[8];
    #pragma unroll
    for (int r = 0; r < 8; r++){ minv[r] = 3.4e38f; mini[r] = 0; }

    for (int ct = 0; ct < K_CODES / BN; ct++){
        const int cbase = ct * BN;
        const float* cp0 = cb + (size_t)(cbase + lrow) * D_DIM + lc4;
        const float* cp1 = cp0 + 64 * D_DIM;

        float cn[8];
        #pragma unroll
        for (int j = 0; j < 8; j++){
            int cl = (j < 4) ? (tx4 + j) : (64 + tx4 + j - 4);
            cn[j] = g_cnorm[cbase + cl];
        }

        unsigned long long acc[8][4];
        #pragma unroll
        for (int r = 0; r < 8; r++)
            #pragma unroll
            for (int p = 0; p < 4; p++) acc[r][p] = 0ull;

        // prefetch chunk 0
        float4 za0 = *(const float4*)zp0;
        float4 za1 = *(const float4*)zp1;
        float4 ca0 = *(const float4*)cp0;
        float4 ca1 = *(const float4*)cp1;

        for (int c = 0; c < D_DIM / BK; c++){
            // store prefetched chunk (transposed) to smem
            sm.t.A[lc4+0][lrow]    = za0.x; sm.t.A[lc4+1][lrow]    = za0.y;
            sm.t.A[lc4+2][lrow]    = za0.z; sm.t.A[lc4+3][lrow]    = za0.w;
            sm.t.A[lc4+0][64+lrow] = za1.x; sm.t.A[lc4+1][64+lrow] = za1.y;
            sm.t.A[lc4+2][64+lrow] = za1.z; sm.t.A[lc4+3][64+lrow] = za1.w;
            sm.t.B[lc4+0][lrow]    = ca0.x; sm.t.B[lc4+1][lrow]    = ca0.y;
            sm.t.B[lc4+2][lrow]    = ca0.z; sm.t.B[lc4+3][lrow]    = ca0.w;
            sm.t.B[lc4+0][64+lrow] = ca1.x; sm.t.B[lc4+1][64+lrow] = ca1.y;
            sm.t.B[lc4+2][64+lrow] = ca1.z; sm.t.B[lc4+3][64+lrow] = ca1.w;
            __syncthreads();

            // prefetch next chunk while computing this one
            if (c + 1 < D_DIM / BK){
                int d = (c + 1) * BK;
                za0 = *(const float4*)(zp0 + d);
                za1 = *(const float4*)(zp1 + d);
                ca0 = *(const float4*)(cp0 + d);
                ca1 = *(const float4*)(cp1 + d);
            }

            #pragma unroll
            for (int k = 0; k < BK; k++){
                float4 a0 = *(const float4*)&sm.t.A[k][ty4];
                float4 a1 = *(const float4*)&sm.t.A[k][64 + ty4];
                ulonglong2 b01 = *(const ulonglong2*)&sm.t.B[k][tx4];
                ulonglong2 b23 = *(const ulonglong2*)&sm.t.B[k][64 + tx4];
                unsigned long long bu0 = b01.x, bu1 = b01.y, bu2 = b23.x, bu3 = b23.y;
                float av[8] = {a0.x,a0.y,a0.z,a0.w,a1.x,a1.y,a1.z,a1.w};
                #pragma unroll
                for (int r = 0; r < 8; r++){
                    unsigned long long a2 = pk2(av[r], av[r]);
                    acc[r][0] = ffma2(a2, bu0, acc[r][0]);
                    acc[r][1] = ffma2(a2, bu1, acc[r][1]);
                    acc[r][2] = ffma2(a2, bu2, acc[r][2]);
                    acc[r][3] = ffma2(a2, bu3, acc[r][3]);
                }
            }
            __syncthreads();
        }

        // epilogue: dist = fp32(fp32(zn+cn) - 2*dot), running argmin (first-index ties)
        #pragma unroll
        for (int r = 0; r < 8; r++){
            #pragma unroll
            for (int p = 0; p < 4; p++){
                float slo, shi; upk2(acc[r][p], slo, shi);
                int j0 = 2 * p;
                int cl0 = (j0 < 4) ? (tx4 + j0) : (64 + tx4 + j0 - 4);
                int gc0 = cbase + cl0;
                float d0 = fmaf(-2.0f, slo, __fadd_rn(znr[r], cn[j0]));
                if (d0 < minv[r]){ minv[r] = d0; mini[r] = gc0; }
                float d1 = fmaf(-2.0f, shi, __fadd_rn(znr[r], cn[j0 + 1]));
                if (d1 < minv[r]){ minv[r] = d1; mini[r] = gc0 + 1; }
            }
        }
    }

    // cross-thread (per-row) reduction with index tie-break
    __syncthreads();
    #pragma unroll
    for (int r = 0; r < 8; r++){
        int rl = (r < 4) ? (ty4 + r) : (64 + ty4 + r - 4);
        sm.r.v[rl][tx]  = minv[r];
        sm.r.id[rl][tx] = mini[r];
    }
    __syncthreads();
    if (tid < 128){
        float bv = sm.r.v[tid][0]; int bi = sm.r.id[tid][0];
        #pragma unroll
        for (int j = 1; j < 16; j++){
            float vv = sm.r.v[tid][j]; int ii = sm.r.id[tid][j];
            if (vv < bv || (vv == bv && ii < bi)){ bv = vv; bi = ii; }
        }
        g_idx[rowbase + tid] = bi;
    }
}

// -------- gather z_q, per-row squared error, index output --------
__global__ void gather_kernel(const float* __restrict__ z, const float* __restrict__ cb,
                              float* __restrict__ out)
{
    __shared__ float red[128];
    int row = blockIdx.x, t = threadIdx.x;
    int id = g_idx[row];
    float4 cv = ((const float4*)(cb + (size_t)id  * D_DIM))[t];
    float4 zv = ((const float4*)(z  + (size_t)row * D_DIM))[t];
    ((float4*)(out + (size_t)row * D_DIM))[t] = cv;   // z_q_ste == z_q numerically
    float dx = zv.x - cv.x, dy = zv.y - cv.y, dz = zv.z - cv.z, dw = zv.w - cv.w;
    red[t] = dx*dx + dy*dy + dz*dz + dw*dw;
    __syncthreads();
    #pragma unroll
    for (int s = 64; s > 0; s >>= 1){
        if (t < s) red[t] += red[t + s];
        __syncthreads();
    }
    if (t == 0){
        g_partial[row] = red[0];
        out[(size_t)N_ROWS * D_DIM + row] = (float)id;   // encoding index
    }
}

// -------- deterministic final loss reduction --------
__global__ void loss_kernel(float* __restrict__ out){
    __shared__ double red[256];
    int t = threadIdx.x;
    double a = 0.0;
    for (int j = t; j < N_ROWS; j += 256) a += (double)g_partial[j];
    red[t] = a; __syncthreads();
    #pragma unroll
    for (int s = 128; s > 0; s >>= 1){
        if (t < s) red[t] += red[t + s];
        __syncthreads();
    }
    if (t == 0){
        float v = (float)(red[0] / ((double)N_ROWS * (double)D_DIM));
        // loss = codebook_loss + 0.25 * commitment_loss, numerically v + 0.25*v
        out[(size_t)N_ROWS * D_DIM + N_ROWS] = __fadd_rn(v, 0.25f * v);
    }
}

extern "C" void kernel_launch(void* const* d_in, const int* in_sizes, int n_in,
                              void* d_out, int out_size)
{
    const float* z  = (const float*)d_in[0];   // [16384, 512]
    const float* cb = (const float*)d_in[1];   // [4096, 512]
    float* out = (float*)d_out;                // [z_q (N*D)] [idx (N)] [loss (1)]

    znorm_kernel<<<N_ROWS / 8, 256>>>(z);      // 8 warps/block, 1 row/warp
    cnorm_kernel<<<K_CODES / 8, 256>>>(cb);
    vq_argmin_kernel<<<N_ROWS / BM, 256>>>(z, cb);
    gather_kernel<<<N_ROWS, 128>>>(z, cb, out);
    loss_kernel<<<1, 256>>>(out);
}